// round 3
// baseline (speedup 1.0000x reference)
#include <cuda_runtime.h>
#include <cstdint>

// Problem constants
#define C_IN   8
#define H_IN   32
#define W_IN   32
#define C_OUT  32
#define KSZ    4
#define STRIDE 2
#define PAD    1
#define HO     16
#define WO     16
#define IN_FEAT  (C_IN * H_IN * W_IN)     // 8192
#define OUT_FEAT (C_OUT * HO * WO)        // 8192
#define WMAT_ELEMS ((unsigned)OUT_FEAT * (unsigned)IN_FEAT)  // 67,108,864

// Output layout in d_out (float32):
//   [0 : 16384)                 out_bounds (lower 8192, upper 8192)
//   [16384 : +67108864)         W_mat [OUT_FEAT, IN_FEAT] row-major
//   [then : +8192)              bias_backsub
#define OFF_WMAT  16384u
#define OFF_BIASB (16384u + WMAT_ELEMS)

// Grid layout:
//   blocks [0, BOUNDS_BLOCKS)            : interval-conv bounds (warp handles 8 r)
//   blocks [BOUNDS_BLOCKS, +WMAT_BLOCKS) : Toeplitz stores, 16 float4 per thread
#define BOUNDS_BLOCKS 128u
#define WMAT_BLOCKS   4096u   // 4096 blk * 256 thr * 16 f4 = 16,777,216 f4

__global__ void __launch_bounds__(256) fused_kernel(
        const float* __restrict__ bounds,
        const float* __restrict__ weight,
        const float* __restrict__ bias,
        float* __restrict__ out) {
    unsigned bid = blockIdx.x;

    if (bid >= BOUNDS_BLOCKS) {
        // ------------------------------------------------------------------
        // Toeplitz stores. Block sb owns rows {2sb, 2sb+1}; thread's column
        // geometry is loop-invariant: c = (it&7)*1024 + tid*4 so
        //   ci = it&7,  h = tid>>3,  w = (tid&7)*4   (h, w fixed per thread).
        // Row-level terms (kh, kw0, masks) precomputed for both rows; the
        // 16-iteration loop is back-to-back STG.128 (__stcs, 268MB >> L2).
        // ------------------------------------------------------------------
        unsigned sb  = bid - BOUNDS_BLOCKS;
        unsigned tid = threadIdx.x;
        int h = (int)(tid >> 3);
        int w = (int)((tid & 7u) << 2);

        float4* dst = reinterpret_cast<float4*>(out + OFF_WMAT)
                      + (size_t)sb * 4096u + tid;

        int r0 = (int)(sb * 2u);
        int co = r0 >> 8;                  // rows 2sb, 2sb+1 share co
        const float* wco = weight + co * (C_IN * KSZ * KSZ);

        int  khv[2];                       // kh*4 if valid, else -1
        int  kwo[2];                       // kw0 offset
        unsigned m[2];                     // 4 validity bits for kw0+0..3
#pragma unroll
        for (int j = 0; j < 2; j++) {
            int r  = r0 + j;
            int ho = (r >> 4) & 15;
            int wo = r & 15;
            int kh  = h - (ho * STRIDE - PAD);
            int kw0 = w - (wo * STRIDE - PAD);
            khv[j] = ((unsigned)kh < (unsigned)KSZ) ? kh * KSZ : -1;
            kwo[j] = kw0;
            unsigned mm = 0;
#pragma unroll
            for (int jj = 0; jj < 4; jj++)
                if ((unsigned)(kw0 + jj) < (unsigned)KSZ) mm |= (1u << jj);
            m[j] = mm;
        }

#pragma unroll
        for (int it = 0; it < 16; it++) {
            int j  = it >> 3;
            int ci = it & 7;
            float4 v = make_float4(0.f, 0.f, 0.f, 0.f);
            if (khv[j] >= 0) {
                const float* p = wco + ci * (KSZ * KSZ) + khv[j] + kwo[j];
                if (m[j] & 1u) v.x = __ldg(p + 0);
                if (m[j] & 2u) v.y = __ldg(p + 1);
                if (m[j] & 4u) v.z = __ldg(p + 2);
                if (m[j] & 8u) v.w = __ldg(p + 3);
            }
            __stcs(dst + it * 256, v);
        }
        return;
    }

    // ----------------------------------------------------------------------
    // Interval conv bounds + bias_backsub. One warp per 8 outputs.
    // Back-substituted bounds equal these exactly; tighten is a no-op.
    // ----------------------------------------------------------------------
    int warp = threadIdx.x >> 5;
    int lane = threadIdx.x & 31;
    int rbase = (int)(bid * 8u + warp) * 8;     // 128 blk * 8 warps * 8 r = 8192

    const float* l = bounds;                    // [8,32,32]
    const float* u = bounds + IN_FEAT;

#pragma unroll 2
    for (int k = 0; k < 8; k++) {
        int r  = rbase + k;
        int co = r >> 8;
        int ho = (r >> 4) & 15;
        int wo = r & 15;
        int h0 = ho * STRIDE - PAD;
        int w0 = wo * STRIDE - PAD;

        float lo = 0.0f, up = 0.0f;
#pragma unroll
        for (int j = 0; j < 4; j++) {
            int t  = lane + j * 32;             // tap: ci*16 + kh*4 + kw
            int ci = t >> 4;
            int kh = (t >> 2) & 3;
            int kw = t & 3;
            int h  = h0 + kh;
            int w  = w0 + kw;
            if ((unsigned)h < (unsigned)H_IN && (unsigned)w < (unsigned)W_IN) {
                float wt = __ldg(weight + (((co * C_IN + ci) * KSZ + kh) * KSZ + kw));
                int in_idx = (ci * H_IN + h) * W_IN + w;
                float lv = __ldg(l + in_idx);
                float uv = __ldg(u + in_idx);
                float wp = fmaxf(wt, 0.0f);
                float wm = fminf(wt, 0.0f);
                lo = fmaf(wp, lv, fmaf(wm, uv, lo));
                up = fmaf(wp, uv, fmaf(wm, lv, up));
            }
        }
#pragma unroll
        for (int off = 16; off > 0; off >>= 1) {
            lo += __shfl_xor_sync(0xFFFFFFFFu, lo, off);
            up += __shfl_xor_sync(0xFFFFFFFFu, up, off);
        }
        if (lane == 0) {
            float b = __ldg(bias + co);
            out[r]             = lo + b;     // lower
            out[OUT_FEAT + r]  = up + b;     // upper
            out[OFF_BIASB + r] = b;          // bias_backsub
        }
    }
}

extern "C" void kernel_launch(void* const* d_in, const int* in_sizes, int n_in,
                              void* d_out, int out_size) {
    const float* bounds = (const float*)d_in[0];  // [2,8,32,32]
    const float* weight = (const float*)d_in[1];  // [32,8,4,4]
    const float* bias   = (const float*)d_in[2];  // [32]
    // d_in[3] = assignment, unused.
    float* out = (float*)d_out;

    fused_kernel<<<BOUNDS_BLOCKS + WMAT_BLOCKS, 256>>>(bounds, weight, bias, out);
}